// round 13
// baseline (speedup 1.0000x reference)
#include <cuda_runtime.h>
#include <cuda_bf16.h>
#include <math.h>
#include <stdint.h>

// Problem dims (fixed by the reference)
#define SEQ    32768
#define NHEAD  8
#define DIN    64
#define DHID   64
#define DOUT   64
#define DMODEL 512                 // NHEAD*DIN
#define NROWS  (SEQ*NHEAD)         // 262144
#define LCH    128                 // scan chunk length = GEMM BM
#define NCH    (NROWS/LCH)         // 2048 chunks
#define NGRP2  16                  // combine groups (merged kernel)
#define GSZ2   (NCH/NGRP2)         // 128 chunks per group

// ---------------- scratch (static __device__, no allocations) ----------------
__device__ float g_x [(size_t)NROWS*DIN];       // 64 MB
__device__ float g_fg[(size_t)NROWS*DHID];      // 64 MB
__device__ float g_hr[(size_t)NROWS*DHID];      // 64 MB
__device__ float g_og[(size_t)NROWS*DHID];      // 64 MB (post-sigmoid)
__device__ float g_o [(size_t)NROWS*DOUT];      // 64 MB
__device__ float g_aggA [NCH*DHID];
__device__ float g_aggB [NCH*DHID];
__device__ float g_carry[NCH*DHID];

__device__ __forceinline__ float sigmoidf_(float x) { return 1.f / (1.f + expf(-x)); }

// ---------------- mma / ldmatrix primitives ----------------
__device__ __forceinline__ void ldsm4(uint32_t r[4], uint32_t a) {
    asm volatile("ldmatrix.sync.aligned.m8n8.x4.shared.b16 {%0,%1,%2,%3},[%4];"
        : "=r"(r[0]), "=r"(r[1]), "=r"(r[2]), "=r"(r[3]) : "r"(a));
}
__device__ __forceinline__ void ldsm4t(uint32_t r[4], uint32_t a) {
    asm volatile("ldmatrix.sync.aligned.m8n8.x4.trans.shared.b16 {%0,%1,%2,%3},[%4];"
        : "=r"(r[0]), "=r"(r[1]), "=r"(r[2]), "=r"(r[3]) : "r"(a));
}
__device__ __forceinline__ void mma16816(float c[4], const uint32_t a[4], const uint32_t b[2]) {
    asm volatile("mma.sync.aligned.m16n8k16.row.col.f32.bf16.bf16.f32 "
        "{%0,%1,%2,%3},{%4,%5,%6,%7},{%8,%9},{%0,%1,%2,%3};"
        : "+f"(c[0]), "+f"(c[1]), "+f"(c[2]), "+f"(c[3])
        : "r"(a[0]), "r"(a[1]), "r"(a[2]), "r"(a[3]), "r"(b[0]), "r"(b[1]));
}
__device__ __forceinline__ void split2(float x, float y, __nv_bfloat162& hi, __nv_bfloat162& lo) {
    __nv_bfloat16 hx = __float2bfloat16(x);
    __nv_bfloat16 hy = __float2bfloat16(y);
    __nv_bfloat16 lx = __float2bfloat16(x - __bfloat162float(hx));
    __nv_bfloat16 ly = __float2bfloat16(y - __bfloat162float(hy));
    hi.x = hx; hi.y = hy;
    lo.x = lx; lo.y = ly;
}
__device__ __forceinline__ void split1(float x, __nv_bfloat16& hi, __nv_bfloat16& lo) {
    hi = __float2bfloat16(x);
    lo = __float2bfloat16(x - __bfloat162float(hi));
}

// ============================================================================
// gemm_big: C = A(MxK) @ B(KxN) + bias, fp32 in/out, bf16 3-term split,
// double-buffered smem (dynamic), one __syncthreads per K-iter.
// BM=128, BN=64, BK=32; 256 threads = 8 warps (4 M x 2 N), warp tile 32x32.
// ============================================================================
#define GB_BM 128
#define GB_BN 64
#define GB_BK 32
#define GB_SA 40
#define GB_SB 72
#define GB_SMEM ((2*(GB_BM*GB_SA + GB_BM*GB_SA + GB_BK*GB_SB + GB_BK*GB_SB))*2)

__global__ void __launch_bounds__(256) gemm_big(
    const float* __restrict__ A, const float* __restrict__ B,
    const float* __restrict__ bias, float* __restrict__ C,
    int M, int N, int K)
{
    constexpr int BM = GB_BM, BN = GB_BN, BK = GB_BK, SA = GB_SA, SB = GB_SB;
    extern __shared__ __nv_bfloat16 dynsm[];
    __nv_bfloat16* sAh = dynsm;                    // [2][BM*SA]
    __nv_bfloat16* sAl = sAh + 2*BM*SA;
    __nv_bfloat16* sBh = sAl + 2*BM*SA;            // [2][BK*SB]
    __nv_bfloat16* sBl = sBh + 2*BK*SB;

    const int tid  = threadIdx.x;
    const int lane = tid & 31, warp = tid >> 5;
    const int wm = warp & 3, wn = warp >> 2;
    const int row0 = blockIdx.y * BM, col0 = blockIdx.x * BN;

    const uint32_t bAh = (uint32_t)__cvta_generic_to_shared(sAh);
    const uint32_t bAl = (uint32_t)__cvta_generic_to_shared(sAl);
    const uint32_t bBh = (uint32_t)__cvta_generic_to_shared(sBh);
    const uint32_t bBl = (uint32_t)__cvta_generic_to_shared(sBl);

    float acc[2][4][4];
#pragma unroll
    for (int i = 0; i < 2; i++)
#pragma unroll
        for (int j = 0; j < 4; j++)
#pragma unroll
            for (int q = 0; q < 4; q++) acc[i][j][q] = 0.f;

    const int lrow = lane & 15;
    const int lcol = (lane >> 4) * 8;

    float4 ar[4], br[2];

    auto ldg = [&](int k0) {
#pragma unroll
        for (int it = 0; it < 4; it++) {
            int c = it*256 + tid; int m = c >> 3; int kc = (c & 7) * 4;
            ar[it] = *(const float4*)(A + (size_t)(row0+m)*K + k0 + kc);
        }
#pragma unroll
        for (int it = 0; it < 2; it++) {
            int c = it*256 + tid; int k = c >> 4; int n4 = (c & 15) * 4;
            br[it] = *(const float4*)(B + (size_t)(k0+k)*N + col0 + n4);
        }
    };
    auto sts = [&](int buf) {
#pragma unroll
        for (int it = 0; it < 4; it++) {
            int c = it*256 + tid; int m = c >> 3; int kc = (c & 7) * 4;
            __nv_bfloat162 h01, l01, h23, l23;
            split2(ar[it].x, ar[it].y, h01, l01);
            split2(ar[it].z, ar[it].w, h23, l23);
            __nv_bfloat16* ph = sAh + buf*BM*SA + m*SA + kc;
            __nv_bfloat16* pl = sAl + buf*BM*SA + m*SA + kc;
            *(__nv_bfloat162*)(ph)     = h01;
            *(__nv_bfloat162*)(ph + 2) = h23;
            *(__nv_bfloat162*)(pl)     = l01;
            *(__nv_bfloat162*)(pl + 2) = l23;
        }
#pragma unroll
        for (int it = 0; it < 2; it++) {
            int c = it*256 + tid; int k = c >> 4; int n4 = (c & 15) * 4;
            __nv_bfloat162 h01, l01, h23, l23;
            split2(br[it].x, br[it].y, h01, l01);
            split2(br[it].z, br[it].w, h23, l23);
            __nv_bfloat16* ph = sBh + buf*BK*SB + k*SB + n4;
            __nv_bfloat16* pl = sBl + buf*BK*SB + k*SB + n4;
            *(__nv_bfloat162*)(ph)     = h01;
            *(__nv_bfloat162*)(ph + 2) = h23;
            *(__nv_bfloat162*)(pl)     = l01;
            *(__nv_bfloat162*)(pl + 2) = l23;
        }
    };

    ldg(0); sts(0); __syncthreads();

    const int nk = K / BK;
    for (int t = 0; t < nk; t++) {
        const int cur = t & 1;
        const bool more = (t + 1 < nk);
        if (more) ldg((t + 1) * BK);

        const uint32_t ao = (uint32_t)(cur * BM * SA * 2);
        const uint32_t bo = (uint32_t)(cur * BK * SB * 2);
#pragma unroll
        for (int ks = 0; ks < 2; ks++) {
            const int kk = ks * 16;
            uint32_t ah[2][4], al[2][4], bh[4][2], bl[4][2];
#pragma unroll
            for (int i = 0; i < 2; i++) {
                uint32_t off = (uint32_t)(((wm*32 + 16*i + lrow) * SA + kk + lcol) * 2);
                ldsm4(ah[i], bAh + ao + off);
                ldsm4(al[i], bAl + ao + off);
            }
#pragma unroll
            for (int j2 = 0; j2 < 2; j2++) {
                uint32_t off = (uint32_t)(((kk + lrow) * SB + wn*32 + 16*j2 + lcol) * 2);
                uint32_t tr[4];
                ldsm4t(tr, bBh + bo + off);
                bh[2*j2][0] = tr[0]; bh[2*j2][1] = tr[1];
                bh[2*j2+1][0] = tr[2]; bh[2*j2+1][1] = tr[3];
                ldsm4t(tr, bBl + bo + off);
                bl[2*j2][0] = tr[0]; bl[2*j2][1] = tr[1];
                bl[2*j2+1][0] = tr[2]; bl[2*j2+1][1] = tr[3];
            }
#pragma unroll
            for (int i = 0; i < 2; i++)
#pragma unroll
                for (int j = 0; j < 4; j++) {
                    mma16816(acc[i][j], ah[i], bh[j]);
                    mma16816(acc[i][j], ah[i], bl[j]);
                    mma16816(acc[i][j], al[i], bh[j]);
                }
        }
        if (more) sts(1 - cur);
        __syncthreads();
    }

    const int group = lane >> 2, tig = lane & 3;
#pragma unroll
    for (int i = 0; i < 2; i++)
#pragma unroll
        for (int j = 0; j < 4; j++) {
            int r  = row0 + wm*32 + 16*i + group;
            int cc = col0 + wn*32 + 8*j + 2*tig;
            float b0 = bias[cc], b1 = bias[cc + 1];
            float2 o0; o0.x = acc[i][j][0] + b0; o0.y = acc[i][j][1] + b1;
            float2 o1; o1.x = acc[i][j][2] + b0; o1.y = acc[i][j][3] + b1;
            *(float2*)(C + (size_t)r       * N + cc) = o0;
            *(float2*)(C + (size_t)(r + 8) * N + cc) = o1;
        }
}

// ============================================================================
// gemm_gates: fused  g = x@W_gates+b ; og = x@W_og+b ; gate nonlinearities ;
//             AND per-chunk scan aggregates (replaces scan_pass1).
// One block per 128-row chunk (== one scan chunk). A staged once; 4 B-tiles:
//   tile 0: fg -> g_fg + smem fgs
//   tile 1: hr m=0..31  -> g_hr + smem hrs
//   tile 2: hr m=32..63 -> g_hr + smem hrs   (top: aggregate scan cols 0-31)
//   tile 3: og -> g_og                        (top: aggregate scan cols 32-63)
// Dynamic smem: 55296 (tiles) + 32768 (fgs) + 16384 (hrs) = 104448 B.
// ============================================================================
#define GG_SA 72
#define GG_SB 72
#define GG_SMEM ((128*GG_SA*2 + 64*GG_SB*2)*2 + 128*64*4 + 128*32*4)

__global__ void __launch_bounds__(256) gemm_gates(
    const float* __restrict__ x,
    const float* __restrict__ Wg, const float* __restrict__ bg,
    const float* __restrict__ Wog, const float* __restrict__ bog)
{
    extern __shared__ __nv_bfloat16 ggsm[];
    __nv_bfloat16* sAh = ggsm;                  // [128][72]
    __nv_bfloat16* sAl = sAh + 128*GG_SA;
    __nv_bfloat16* sBh = sAl + 128*GG_SA;       // [64][72]
    __nv_bfloat16* sBl = sBh + 64*GG_SB;
    float* fgs = (float*)(sBl + 64*GG_SB);      // [128][64] fp32
    float* hrs = fgs + 128*64;                  // [128][32] fp32 (current half)

    const int tid  = threadIdx.x;
    const int lane = tid & 31, warp = tid >> 5;
    const int wm = warp & 3, wn = warp >> 2;
    const int row0 = blockIdx.x * 128;

    const uint32_t bAh = (uint32_t)__cvta_generic_to_shared(sAh);
    const uint32_t bAl = (uint32_t)__cvta_generic_to_shared(sAl);
    const uint32_t bBh = (uint32_t)__cvta_generic_to_shared(sBh);
    const uint32_t bBl = (uint32_t)__cvta_generic_to_shared(sBl);

    const int lrow = lane & 15;
    const int lcol = (lane >> 4) * 8;
    const int group = lane >> 2, tig = lane & 3;

    // ---- stage A once: x rows row0..row0+127, K=64, hi/lo split ----
#pragma unroll
    for (int it = 0; it < 8; it++) {
        int c  = it*256 + tid;
        int m  = c >> 4;
        int kc = (c & 15) * 4;
        float4 v = *(const float4*)(x + (size_t)(row0+m)*64 + kc);
        __nv_bfloat162 h01, l01, h23, l23;
        split2(v.x, v.y, h01, l01);
        split2(v.z, v.w, h23, l23);
        *(__nv_bfloat162*)(sAh + m*GG_SA + kc)     = h01;
        *(__nv_bfloat162*)(sAh + m*GG_SA + kc + 2) = h23;
        *(__nv_bfloat162*)(sAl + m*GG_SA + kc)     = l01;
        *(__nv_bfloat162*)(sAl + m*GG_SA + kc + 2) = l23;
    }

    // ---- loop over 4 B-tiles, A resident ----
    for (int tile = 0; tile < 4; tile++) {
        __syncthreads();   // prev epilogue done (covers fgs/hrs writes too)

        // aggregate scan for the half produced by the PREVIOUS tile
        if (tile >= 2 && tid < 32) {
            int j = (tile - 2) * 32 + tid;
            float Aacc = 1.f, Bacc = 0.f;
#pragma unroll 8
            for (int t = 0; t < 128; t++) {
                float a = fgs[t*64 + j];
                float h = hrs[t*32 + tid];
                Bacc = fmaf(Bacc, a, h);
                Aacc *= a;
            }
            g_aggA[blockIdx.x*DHID + j] = Aacc;
            g_aggB[blockIdx.x*DHID + j] = Bacc;
        }

        // stage B for this tile
        if (tile == 0) {
#pragma unroll
            for (int it = 0; it < 4; it++) {
                int c = it*256 + tid; int k = c >> 4; int n4 = (c & 15) * 4;
                float4 v = *(const float4*)(Wg + (size_t)k*192 + n4);
                __nv_bfloat162 h01, l01, h23, l23;
                split2(v.x, v.y, h01, l01);
                split2(v.z, v.w, h23, l23);
                *(__nv_bfloat162*)(sBh + k*GG_SB + n4)     = h01;
                *(__nv_bfloat162*)(sBh + k*GG_SB + n4 + 2) = h23;
                *(__nv_bfloat162*)(sBl + k*GG_SB + n4)     = l01;
                *(__nv_bfloat162*)(sBl + k*GG_SB + n4 + 2) = l23;
            }
        } else if (tile == 3) {
#pragma unroll
            for (int it = 0; it < 4; it++) {
                int c = it*256 + tid; int k = c >> 4; int n4 = (c & 15) * 4;
                float4 v = *(const float4*)(Wog + (size_t)k*64 + n4);
                __nv_bfloat162 h01, l01, h23, l23;
                split2(v.x, v.y, h01, l01);
                split2(v.z, v.w, h23, l23);
                *(__nv_bfloat162*)(sBh + k*GG_SB + n4)     = h01;
                *(__nv_bfloat162*)(sBh + k*GG_SB + n4 + 2) = h23;
                *(__nv_bfloat162*)(sBl + k*GG_SB + n4)     = l01;
                *(__nv_bfloat162*)(sBl + k*GG_SB + n4 + 2) = l23;
            }
        } else {
            const int base = (tile - 1) * 32;
#pragma unroll
            for (int it = 0; it < 8; it++) {
                int c = it*256 + tid;
                int k = c >> 5;
                int m = c & 31;
                float a  = Wg[(size_t)k*192 + 64  + base + m];
                float b2 = Wg[(size_t)k*192 + 128 + base + m];
                __nv_bfloat162 h, l;
                split2(a, b2, h, l);
                *(__nv_bfloat162*)(sBh + k*GG_SB + 2*m) = h;
                *(__nv_bfloat162*)(sBl + k*GG_SB + 2*m) = l;
            }
        }
        __syncthreads();

        float acc[2][4][4];
#pragma unroll
        for (int i = 0; i < 2; i++)
#pragma unroll
            for (int j = 0; j < 4; j++)
#pragma unroll
                for (int q = 0; q < 4; q++) acc[i][j][q] = 0.f;

#pragma unroll
        for (int ks = 0; ks < 4; ks++) {
            const int kk = ks * 16;
            uint32_t ah[2][4], al[2][4], bh[4][2], bl[4][2];
#pragma unroll
            for (int i = 0; i < 2; i++) {
                uint32_t off = (uint32_t)(((wm*32 + 16*i + lrow) * GG_SA + kk + lcol) * 2);
                ldsm4(ah[i], bAh + off);
                ldsm4(al[i], bAl + off);
            }
#pragma unroll
            for (int j2 = 0; j2 < 2; j2++) {
                uint32_t off = (uint32_t)(((kk + lrow) * GG_SB + wn*32 + 16*j2 + lcol) * 2);
                uint32_t tr[4];
                ldsm4t(tr, bBh + off);
                bh[2*j2][0] = tr[0]; bh[2*j2][1] = tr[1];
                bh[2*j2+1][0] = tr[2]; bh[2*j2+1][1] = tr[3];
                ldsm4t(tr, bBl + off);
                bl[2*j2][0] = tr[0]; bl[2*j2][1] = tr[1];
                bl[2*j2+1][0] = tr[2]; bl[2*j2+1][1] = tr[3];
            }
#pragma unroll
            for (int i = 0; i < 2; i++)
#pragma unroll
                for (int j = 0; j < 4; j++) {
                    mma16816(acc[i][j], ah[i], bh[j]);
                    mma16816(acc[i][j], ah[i], bl[j]);
                    mma16816(acc[i][j], al[i], bh[j]);
                }
        }

        // per-tile epilogue (global + smem mirrors for fg/hr)
#pragma unroll
        for (int i = 0; i < 2; i++)
#pragma unroll
            for (int j = 0; j < 4; j++) {
                int rl = wm*32 + 16*i + group;          // local row 0..127
                int r  = row0 + rl;
                int cc = wn*32 + 8*j + 2*tig;
                if (tile == 0) {
                    float b0 = bg[cc], b1 = bg[cc+1];
                    float2 o0; o0.x = sigmoidf_(acc[i][j][0] + b0); o0.y = sigmoidf_(acc[i][j][1] + b1);
                    float2 o1; o1.x = sigmoidf_(acc[i][j][2] + b0); o1.y = sigmoidf_(acc[i][j][3] + b1);
                    *(float2*)(g_fg + (size_t)r       * DHID + cc) = o0;
                    *(float2*)(g_fg + (size_t)(r + 8) * DHID + cc) = o1;
                    *(float2*)(fgs + rl*64 + cc)       = o0;
                    *(float2*)(fgs + (rl + 8)*64 + cc) = o1;
                } else if (tile == 3) {
                    float b0 = bog[cc], b1 = bog[cc+1];
                    float2 o0; o0.x = sigmoidf_(acc[i][j][0] + b0); o0.y = sigmoidf_(acc[i][j][1] + b1);
                    float2 o1; o1.x = sigmoidf_(acc[i][j][2] + b0); o1.y = sigmoidf_(acc[i][j][3] + b1);
                    *(float2*)(g_og + (size_t)r       * DHID + cc) = o0;
                    *(float2*)(g_og + (size_t)(r + 8) * DHID + cc) = o1;
                } else {
                    int mg = (tile - 1) * 32 + (cc >> 1);
                    float b0 = bg[64 + mg], b1 = bg[128 + mg];
                    float hr0 = sigmoidf_(acc[i][j][0] + b0) * tanhf(acc[i][j][1] + b1);
                    float hr1 = sigmoidf_(acc[i][j][2] + b0) * tanhf(acc[i][j][3] + b1);
                    g_hr[(size_t)r       * DHID + mg] = hr0;
                    g_hr[(size_t)(r + 8) * DHID + mg] = hr1;
                    hrs[rl*32 + (mg & 31)]       = hr0;
                    hrs[(rl + 8)*32 + (mg & 31)] = hr1;
                }
            }
    }
}

// ============================================================================
// combine_all: hierarchical carry combine in ONE kernel (1 block, 1024 thr).
// pass1: 16 groups x 64 cols aggregate over 128 chunks each;
// pass2: 64 threads serial over 16 groups (smem);
// pass3: per-chunk carries written to g_carry.
// ============================================================================
__global__ void __launch_bounds__(1024) combine_all()
{
    __shared__ float sA[NGRP2*DHID], sB[NGRP2*DHID], sC[NGRP2*DHID];
    const int tid = threadIdx.x;
    const int g = tid >> 6, j = tid & 63;

    float A = 1.f, B = 0.f;
#pragma unroll 8
    for (int c = 0; c < GSZ2; c++) {
        int idx = (g*GSZ2 + c)*DHID + j;
        float a = g_aggA[idx], b = g_aggB[idx];
        B = fmaf(B, a, b);
        A *= a;
    }
    sA[g*DHID + j] = A;
    sB[g*DHID + j] = B;
    __syncthreads();

    if (tid < DHID) {
        float c = 0.f;
#pragma unroll
        for (int g2 = 0; g2 < NGRP2; g2++) {
            sC[g2*DHID + tid] = c;
            c = fmaf(c, sA[g2*DHID + tid], sB[g2*DHID + tid]);
        }
    }
    __syncthreads();

    float c = sC[g*DHID + j];
#pragma unroll 8
    for (int cc = 0; cc < GSZ2; cc++) {
        int idx = (g*GSZ2 + cc)*DHID + j;
        g_carry[idx] = c;
        c = fmaf(c, g_aggA[idx], g_aggB[idx]);
    }
}

// ============================================================================
// fused: per-chunk scan -> y = og*c (split bf16 into smem) -> o = y@W_c + b_c
// ============================================================================
#define LA_SY 72
#define LA_SW 72
#define LA_SMEM ((128*LA_SY*2 + 64*LA_SW*2)*2)

__global__ void __launch_bounds__(256) lstm_apply_gemm(
    const float* __restrict__ Wc, const float* __restrict__ bc)
{
    extern __shared__ __nv_bfloat16 dynsm2[];
    __nv_bfloat16* sYh = dynsm2;
    __nv_bfloat16* sYl = sYh + 128*LA_SY;
    __nv_bfloat16* sWh = sYl + 128*LA_SY;
    __nv_bfloat16* sWl = sWh + 64*LA_SW;

    const int b   = blockIdx.x;
    const int tid = threadIdx.x;
    const int lane = tid & 31, warp = tid >> 5;
    const int wm = warp & 3, wn = warp >> 2;

#pragma unroll
    for (int it = 0; it < 4; it++) {
        int c = it*256 + tid; int k = c >> 4; int n4 = (c & 15) * 4;
        float4 v = *(const float4*)(Wc + (size_t)k*64 + n4);
        __nv_bfloat162 h01, l01, h23, l23;
        split2(v.x, v.y, h01, l01);
        split2(v.z, v.w, h23, l23);
        *(__nv_bfloat162*)(sWh + k*LA_SW + n4)     = h01;
        *(__nv_bfloat162*)(sWh + k*LA_SW + n4 + 2) = h23;
        *(__nv_bfloat162*)(sWl + k*LA_SW + n4)     = l01;
        *(__nv_bfloat162*)(sWl + k*LA_SW + n4 + 2) = l23;
    }

    if (tid < 64) {
        int j = tid;
        float c = g_carry[b*DHID + j];
        size_t base = (size_t)b * LCH * DHID + j;
#pragma unroll 8
        for (int t = 0; t < LCH; t++) {
            size_t idx = base + (size_t)t * DHID;
            c = fmaf(c, g_fg[idx], g_hr[idx]);
            float y = g_og[idx] * c;
            __nv_bfloat16 yh, yl;
            split1(y, yh, yl);
            sYh[t*LA_SY + j] = yh;
            sYl[t*LA_SY + j] = yl;
        }
    }
    __syncthreads();

    const uint32_t bYh = (uint32_t)__cvta_generic_to_shared(sYh);
    const uint32_t bYl = (uint32_t)__cvta_generic_to_shared(sYl);
    const uint32_t bWh = (uint32_t)__cvta_generic_to_shared(sWh);
    const uint32_t bWl = (uint32_t)__cvta_generic_to_shared(sWl);

    float acc[2][4][4];
#pragma unroll
    for (int i = 0; i < 2; i++)
#pragma unroll
        for (int j = 0; j < 4; j++)
#pragma unroll
            for (int q = 0; q < 4; q++) acc[i][j][q] = 0.f;

    const int lrow = lane & 15;
    const int lcol = (lane >> 4) * 8;

#pragma unroll
    for (int ks = 0; ks < 4; ks++) {
        const int kk = ks * 16;
        uint32_t ah[2][4], al[2][4], bh[4][2], bl[4][2];
#pragma unroll
        for (int i = 0; i < 2; i++) {
            uint32_t off = (uint32_t)(((wm*32 + 16*i + lrow) * LA_SY + kk + lcol) * 2);
            ldsm4(ah[i], bYh + off);
            ldsm4(al[i], bYl + off);
        }
#pragma unroll
        for (int j2 = 0; j2 < 2; j2++) {
            uint32_t off = (uint32_t)(((kk + lrow) * LA_SW + wn*32 + 16*j2 + lcol) * 2);
            uint32_t tr[4];
            ldsm4t(tr, bWh + off);
            bh[2*j2][0] = tr[0]; bh[2*j2][1] = tr[1];
            bh[2*j2+1][0] = tr[2]; bh[2*j2+1][1] = tr[3];
            ldsm4t(tr, bWl + off);
            bl[2*j2][0] = tr[0]; bl[2*j2][1] = tr[1];
            bl[2*j2+1][0] = tr[2]; bl[2*j2+1][1] = tr[3];
        }
#pragma unroll
        for (int i = 0; i < 2; i++)
#pragma unroll
            for (int j = 0; j < 4; j++) {
                mma16816(acc[i][j], ah[i], bh[j]);
                mma16816(acc[i][j], ah[i], bl[j]);
                mma16816(acc[i][j], al[i], bh[j]);
            }
    }

    const int group = lane >> 2, tig = lane & 3;
#pragma unroll
    for (int i = 0; i < 2; i++)
#pragma unroll
        for (int j = 0; j < 4; j++) {
            int r  = b*128 + wm*32 + 16*i + group;
            int cc = wn*32 + 8*j + 2*tig;
            float b0 = bc[cc], b1 = bc[cc+1];
            float2 o0; o0.x = acc[i][j][0] + b0; o0.y = acc[i][j][1] + b1;
            float2 o1; o1.x = acc[i][j][2] + b0; o1.y = acc[i][j][3] + b1;
            *(float2*)(g_o + (size_t)r       * DOUT + cc) = o0;
            *(float2*)(g_o + (size_t)(r + 8) * DOUT + cc) = o1;
        }
}

// ---------------- launch ----------------
extern "C" void kernel_launch(void* const* d_in, const int* in_sizes, int n_in,
                              void* d_out, int out_size)
{
    const float* inputs  = (const float*)d_in[0];
    const float* W_in    = (const float*)d_in[1];
    const float* b_in    = (const float*)d_in[2];
    const float* W_gates = (const float*)d_in[3];
    const float* b_gates = (const float*)d_in[4];
    const float* W_og    = (const float*)d_in[5];
    const float* b_og    = (const float*)d_in[6];
    const float* W_c     = (const float*)d_in[7];
    const float* b_c     = (const float*)d_in[8];
    const float* W_out   = (const float*)d_in[9];
    const float* b_out   = (const float*)d_in[10];
    float* out = (float*)d_out;

    float *px, *po;
    cudaGetSymbolAddress((void**)&px, g_x);
    cudaGetSymbolAddress((void**)&po, g_o);

    cudaFuncSetAttribute(gemm_big, cudaFuncAttributeMaxDynamicSharedMemorySize, GB_SMEM);
    cudaFuncSetAttribute(gemm_gates, cudaFuncAttributeMaxDynamicSharedMemorySize, GG_SMEM);
    cudaFuncSetAttribute(lstm_apply_gemm, cudaFuncAttributeMaxDynamicSharedMemorySize, LA_SMEM);

    dim3 blk(256);

    // 1) x = inputs @ W_in + b_in           (32768 x 512 x 512)
    gemm_big<<<dim3(DMODEL/GB_BN, SEQ/GB_BM), blk, GB_SMEM>>>(
        inputs, W_in, b_in, px, SEQ, DMODEL, DMODEL);

    // 2) fused gates + per-chunk scan aggregates
    gemm_gates<<<NROWS/128, blk, GG_SMEM>>>(px, W_gates, b_gates, W_og, b_og);

    // 3) hierarchical carry combine (single kernel)
    combine_all<<<1, 1024>>>();

    // 4) fused scan-apply + o = y @ W_c + b_c
    lstm_apply_gemm<<<NCH, blk, LA_SMEM>>>(W_c, b_c);

    // 5) out = o @ W_out + b_out            (32768 x 512 x 512)
    gemm_big<<<dim3(DMODEL/GB_BN, SEQ/GB_BM), blk, GB_SMEM>>>(
        po, W_out, b_out, out, SEQ, DMODEL, DMODEL);
}

// round 14
// speedup vs baseline: 1.0812x; 1.0812x over previous
#include <cuda_runtime.h>
#include <cuda_bf16.h>
#include <math.h>
#include <stdint.h>

// Problem dims (fixed by the reference)
#define SEQ    32768
#define NHEAD  8
#define DIN    64
#define DHID   64
#define DOUT   64
#define DMODEL 512                 // NHEAD*DIN
#define NROWS  (SEQ*NHEAD)         // 262144
#define LCH    128                 // scan chunk length = GEMM BM
#define NCH    (NROWS/LCH)         // 2048 chunks
#define NGRP   32                  // combine groups
#define GSZ    (NCH/NGRP)          // 64 chunks per group

// ---------------- scratch (static __device__, no allocations) ----------------
__device__ float g_x [(size_t)NROWS*DIN];       // 64 MB
__device__ float g_fg[(size_t)NROWS*DHID];      // 64 MB
__device__ float g_hr[(size_t)NROWS*DHID];      // 64 MB
__device__ float g_og[(size_t)NROWS*DHID];      // 64 MB (post-sigmoid)
__device__ float g_o [(size_t)NROWS*DOUT];      // 64 MB
__device__ float g_aggA [NCH*DHID];
__device__ float g_aggB [NCH*DHID];
__device__ float g_carry[NCH*DHID];
__device__ float g_gA[NGRP*DHID];
__device__ float g_gB[NGRP*DHID];
__device__ float g_gc[NGRP*DHID];

__device__ __forceinline__ float sigmoidf_(float x) { return 1.f / (1.f + expf(-x)); }

// ---------------- mma / ldmatrix primitives ----------------
__device__ __forceinline__ void ldsm4(uint32_t r[4], uint32_t a) {
    asm volatile("ldmatrix.sync.aligned.m8n8.x4.shared.b16 {%0,%1,%2,%3},[%4];"
        : "=r"(r[0]), "=r"(r[1]), "=r"(r[2]), "=r"(r[3]) : "r"(a));
}
__device__ __forceinline__ void ldsm4t(uint32_t r[4], uint32_t a) {
    asm volatile("ldmatrix.sync.aligned.m8n8.x4.trans.shared.b16 {%0,%1,%2,%3},[%4];"
        : "=r"(r[0]), "=r"(r[1]), "=r"(r[2]), "=r"(r[3]) : "r"(a));
}
__device__ __forceinline__ void mma16816(float c[4], const uint32_t a[4], const uint32_t b[2]) {
    asm volatile("mma.sync.aligned.m16n8k16.row.col.f32.bf16.bf16.f32 "
        "{%0,%1,%2,%3},{%4,%5,%6,%7},{%8,%9},{%0,%1,%2,%3};"
        : "+f"(c[0]), "+f"(c[1]), "+f"(c[2]), "+f"(c[3])
        : "r"(a[0]), "r"(a[1]), "r"(a[2]), "r"(a[3]), "r"(b[0]), "r"(b[1]));
}
__device__ __forceinline__ void split2(float x, float y, __nv_bfloat162& hi, __nv_bfloat162& lo) {
    __nv_bfloat16 hx = __float2bfloat16(x);
    __nv_bfloat16 hy = __float2bfloat16(y);
    __nv_bfloat16 lx = __float2bfloat16(x - __bfloat162float(hx));
    __nv_bfloat16 ly = __float2bfloat16(y - __bfloat162float(hy));
    hi.x = hx; hi.y = hy;
    lo.x = lx; lo.y = ly;
}
__device__ __forceinline__ void split1(float x, __nv_bfloat16& hi, __nv_bfloat16& lo) {
    hi = __float2bfloat16(x);
    lo = __float2bfloat16(x - __bfloat162float(hi));
}

// ============================================================================
// gemm_big: C = A(MxK) @ B(KxN) + bias, fp32 in/out, bf16 3-term split,
// double-buffered smem (dynamic), one __syncthreads per K-iter.
// BM=128, BN=64, BK=32; 256 threads = 8 warps (4 M x 2 N), warp tile 32x32.
// ============================================================================
#define GB_BM 128
#define GB_BN 64
#define GB_BK 32
#define GB_SA 40
#define GB_SB 72
#define GB_SMEM ((2*(GB_BM*GB_SA + GB_BM*GB_SA + GB_BK*GB_SB + GB_BK*GB_SB))*2)

__global__ void __launch_bounds__(256) gemm_big(
    const float* __restrict__ A, const float* __restrict__ B,
    const float* __restrict__ bias, float* __restrict__ C,
    int M, int N, int K)
{
    constexpr int BM = GB_BM, BN = GB_BN, BK = GB_BK, SA = GB_SA, SB = GB_SB;
    extern __shared__ __nv_bfloat16 dynsm[];
    __nv_bfloat16* sAh = dynsm;                    // [2][BM*SA]
    __nv_bfloat16* sAl = sAh + 2*BM*SA;
    __nv_bfloat16* sBh = sAl + 2*BM*SA;            // [2][BK*SB]
    __nv_bfloat16* sBl = sBh + 2*BK*SB;

    const int tid  = threadIdx.x;
    const int lane = tid & 31, warp = tid >> 5;
    const int wm = warp & 3, wn = warp >> 2;
    const int row0 = blockIdx.y * BM, col0 = blockIdx.x * BN;

    const uint32_t bAh = (uint32_t)__cvta_generic_to_shared(sAh);
    const uint32_t bAl = (uint32_t)__cvta_generic_to_shared(sAl);
    const uint32_t bBh = (uint32_t)__cvta_generic_to_shared(sBh);
    const uint32_t bBl = (uint32_t)__cvta_generic_to_shared(sBl);

    float acc[2][4][4];
#pragma unroll
    for (int i = 0; i < 2; i++)
#pragma unroll
        for (int j = 0; j < 4; j++)
#pragma unroll
            for (int q = 0; q < 4; q++) acc[i][j][q] = 0.f;

    const int lrow = lane & 15;
    const int lcol = (lane >> 4) * 8;

    float4 ar[4], br[2];

    auto ldg = [&](int k0) {
#pragma unroll
        for (int it = 0; it < 4; it++) {
            int c = it*256 + tid; int m = c >> 3; int kc = (c & 7) * 4;
            ar[it] = *(const float4*)(A + (size_t)(row0+m)*K + k0 + kc);
        }
#pragma unroll
        for (int it = 0; it < 2; it++) {
            int c = it*256 + tid; int k = c >> 4; int n4 = (c & 15) * 4;
            br[it] = *(const float4*)(B + (size_t)(k0+k)*N + col0 + n4);
        }
    };
    auto sts = [&](int buf) {
#pragma unroll
        for (int it = 0; it < 4; it++) {
            int c = it*256 + tid; int m = c >> 3; int kc = (c & 7) * 4;
            __nv_bfloat162 h01, l01, h23, l23;
            split2(ar[it].x, ar[it].y, h01, l01);
            split2(ar[it].z, ar[it].w, h23, l23);
            __nv_bfloat16* ph = sAh + buf*BM*SA + m*SA + kc;
            __nv_bfloat16* pl = sAl + buf*BM*SA + m*SA + kc;
            *(__nv_bfloat162*)(ph)     = h01;
            *(__nv_bfloat162*)(ph + 2) = h23;
            *(__nv_bfloat162*)(pl)     = l01;
            *(__nv_bfloat162*)(pl + 2) = l23;
        }
#pragma unroll
        for (int it = 0; it < 2; it++) {
            int c = it*256 + tid; int k = c >> 4; int n4 = (c & 15) * 4;
            __nv_bfloat162 h01, l01, h23, l23;
            split2(br[it].x, br[it].y, h01, l01);
            split2(br[it].z, br[it].w, h23, l23);
            __nv_bfloat16* ph = sBh + buf*BK*SB + k*SB + n4;
            __nv_bfloat16* pl = sBl + buf*BK*SB + k*SB + n4;
            *(__nv_bfloat162*)(ph)     = h01;
            *(__nv_bfloat162*)(ph + 2) = h23;
            *(__nv_bfloat162*)(pl)     = l01;
            *(__nv_bfloat162*)(pl + 2) = l23;
        }
    };

    ldg(0); sts(0); __syncthreads();

    const int nk = K / BK;
    for (int t = 0; t < nk; t++) {
        const int cur = t & 1;
        const bool more = (t + 1 < nk);
        if (more) ldg((t + 1) * BK);

        const uint32_t ao = (uint32_t)(cur * BM * SA * 2);
        const uint32_t bo = (uint32_t)(cur * BK * SB * 2);
#pragma unroll
        for (int ks = 0; ks < 2; ks++) {
            const int kk = ks * 16;
            uint32_t ah[2][4], al[2][4], bh[4][2], bl[4][2];
#pragma unroll
            for (int i = 0; i < 2; i++) {
                uint32_t off = (uint32_t)(((wm*32 + 16*i + lrow) * SA + kk + lcol) * 2);
                ldsm4(ah[i], bAh + ao + off);
                ldsm4(al[i], bAl + ao + off);
            }
#pragma unroll
            for (int j2 = 0; j2 < 2; j2++) {
                uint32_t off = (uint32_t)(((kk + lrow) * SB + wn*32 + 16*j2 + lcol) * 2);
                uint32_t tr[4];
                ldsm4t(tr, bBh + bo + off);
                bh[2*j2][0] = tr[0]; bh[2*j2][1] = tr[1];
                bh[2*j2+1][0] = tr[2]; bh[2*j2+1][1] = tr[3];
                ldsm4t(tr, bBl + bo + off);
                bl[2*j2][0] = tr[0]; bl[2*j2][1] = tr[1];
                bl[2*j2+1][0] = tr[2]; bl[2*j2+1][1] = tr[3];
            }
#pragma unroll
            for (int i = 0; i < 2; i++)
#pragma unroll
                for (int j = 0; j < 4; j++) {
                    mma16816(acc[i][j], ah[i], bh[j]);
                    mma16816(acc[i][j], ah[i], bl[j]);
                    mma16816(acc[i][j], al[i], bh[j]);
                }
        }
        if (more) sts(1 - cur);
        __syncthreads();
    }

    const int group = lane >> 2, tig = lane & 3;
#pragma unroll
    for (int i = 0; i < 2; i++)
#pragma unroll
        for (int j = 0; j < 4; j++) {
            int r  = row0 + wm*32 + 16*i + group;
            int cc = col0 + wn*32 + 8*j + 2*tig;
            float b0 = bias[cc], b1 = bias[cc + 1];
            float2 o0; o0.x = acc[i][j][0] + b0; o0.y = acc[i][j][1] + b1;
            float2 o1; o1.x = acc[i][j][2] + b0; o1.y = acc[i][j][3] + b1;
            *(float2*)(C + (size_t)r       * N + cc) = o0;
            *(float2*)(C + (size_t)(r + 8) * N + cc) = o1;
        }
}

// ============================================================================
// gemm_gates: fused  g = x@W_gates+b ; og = x@W_og+b ; gate nonlinearities.
// One block per 128-row chunk. A staged once, 4 sequential B-tiles.
// (identical to round-9 passing version)
// ============================================================================
#define GG_SA 72
#define GG_SB 72
#define GG_SMEM ((128*GG_SA*2 + 64*GG_SB*2)*2)

__global__ void __launch_bounds__(256) gemm_gates(
    const float* __restrict__ x,
    const float* __restrict__ Wg, const float* __restrict__ bg,
    const float* __restrict__ Wog, const float* __restrict__ bog)
{
    extern __shared__ __nv_bfloat16 ggsm[];
    __nv_bfloat16* sAh = ggsm;                  // [128][72]
    __nv_bfloat16* sAl = sAh + 128*GG_SA;
    __nv_bfloat16* sBh = sAl + 128*GG_SA;       // [64][72]
    __nv_bfloat16* sBl = sBh + 64*GG_SB;

    const int tid  = threadIdx.x;
    const int lane = tid & 31, warp = tid >> 5;
    const int wm = warp & 3, wn = warp >> 2;
    const int row0 = blockIdx.x * 128;

    const uint32_t bAh = (uint32_t)__cvta_generic_to_shared(sAh);
    const uint32_t bAl = (uint32_t)__cvta_generic_to_shared(sAl);
    const uint32_t bBh = (uint32_t)__cvta_generic_to_shared(sBh);
    const uint32_t bBl = (uint32_t)__cvta_generic_to_shared(sBl);

    const int lrow = lane & 15;
    const int lcol = (lane >> 4) * 8;
    const int group = lane >> 2, tig = lane & 3;

    // ---- stage A once: x rows row0..row0+127, K=64, hi/lo split ----
#pragma unroll
    for (int it = 0; it < 8; it++) {
        int c  = it*256 + tid;
        int m  = c >> 4;
        int kc = (c & 15) * 4;
        float4 v = *(const float4*)(x + (size_t)(row0+m)*64 + kc);
        __nv_bfloat162 h01, l01, h23, l23;
        split2(v.x, v.y, h01, l01);
        split2(v.z, v.w, h23, l23);
        *(__nv_bfloat162*)(sAh + m*GG_SA + kc)     = h01;
        *(__nv_bfloat162*)(sAh + m*GG_SA + kc + 2) = h23;
        *(__nv_bfloat162*)(sAl + m*GG_SA + kc)     = l01;
        *(__nv_bfloat162*)(sAl + m*GG_SA + kc + 2) = l23;
    }

    // ---- loop over 4 B-tiles, A resident ----
    for (int tile = 0; tile < 4; tile++) {
        __syncthreads();

        if (tile == 0) {
#pragma unroll
            for (int it = 0; it < 4; it++) {
                int c = it*256 + tid; int k = c >> 4; int n4 = (c & 15) * 4;
                float4 v = *(const float4*)(Wg + (size_t)k*192 + n4);
                __nv_bfloat162 h01, l01, h23, l23;
                split2(v.x, v.y, h01, l01);
                split2(v.z, v.w, h23, l23);
                *(__nv_bfloat162*)(sBh + k*GG_SB + n4)     = h01;
                *(__nv_bfloat162*)(sBh + k*GG_SB + n4 + 2) = h23;
                *(__nv_bfloat162*)(sBl + k*GG_SB + n4)     = l01;
                *(__nv_bfloat162*)(sBl + k*GG_SB + n4 + 2) = l23;
            }
        } else if (tile == 3) {
#pragma unroll
            for (int it = 0; it < 4; it++) {
                int c = it*256 + tid; int k = c >> 4; int n4 = (c & 15) * 4;
                float4 v = *(const float4*)(Wog + (size_t)k*64 + n4);
                __nv_bfloat162 h01, l01, h23, l23;
                split2(v.x, v.y, h01, l01);
                split2(v.z, v.w, h23, l23);
                *(__nv_bfloat162*)(sBh + k*GG_SB + n4)     = h01;
                *(__nv_bfloat162*)(sBh + k*GG_SB + n4 + 2) = h23;
                *(__nv_bfloat162*)(sBl + k*GG_SB + n4)     = l01;
                *(__nv_bfloat162*)(sBl + k*GG_SB + n4 + 2) = l23;
            }
        } else {
            const int base = (tile - 1) * 32;
#pragma unroll
            for (int it = 0; it < 8; it++) {
                int c = it*256 + tid;
                int k = c >> 5;
                int m = c & 31;
                float a  = Wg[(size_t)k*192 + 64  + base + m];
                float b2 = Wg[(size_t)k*192 + 128 + base + m];
                __nv_bfloat162 h, l;
                split2(a, b2, h, l);
                *(__nv_bfloat162*)(sBh + k*GG_SB + 2*m) = h;
                *(__nv_bfloat162*)(sBl + k*GG_SB + 2*m) = l;
            }
        }
        __syncthreads();

        float acc[2][4][4];
#pragma unroll
        for (int i = 0; i < 2; i++)
#pragma unroll
            for (int j = 0; j < 4; j++)
#pragma unroll
                for (int q = 0; q < 4; q++) acc[i][j][q] = 0.f;

#pragma unroll
        for (int ks = 0; ks < 4; ks++) {
            const int kk = ks * 16;
            uint32_t ah[2][4], al[2][4], bh[4][2], bl[4][2];
#pragma unroll
            for (int i = 0; i < 2; i++) {
                uint32_t off = (uint32_t)(((wm*32 + 16*i + lrow) * GG_SA + kk + lcol) * 2);
                ldsm4(ah[i], bAh + off);
                ldsm4(al[i], bAl + off);
            }
#pragma unroll
            for (int j2 = 0; j2 < 2; j2++) {
                uint32_t off = (uint32_t)(((kk + lrow) * GG_SB + wn*32 + 16*j2 + lcol) * 2);
                uint32_t tr[4];
                ldsm4t(tr, bBh + off);
                bh[2*j2][0] = tr[0]; bh[2*j2][1] = tr[1];
                bh[2*j2+1][0] = tr[2]; bh[2*j2+1][1] = tr[3];
                ldsm4t(tr, bBl + off);
                bl[2*j2][0] = tr[0]; bl[2*j2][1] = tr[1];
                bl[2*j2+1][0] = tr[2]; bl[2*j2+1][1] = tr[3];
            }
#pragma unroll
            for (int i = 0; i < 2; i++)
#pragma unroll
                for (int j = 0; j < 4; j++) {
                    mma16816(acc[i][j], ah[i], bh[j]);
                    mma16816(acc[i][j], ah[i], bl[j]);
                    mma16816(acc[i][j], al[i], bh[j]);
                }
        }

        // per-tile epilogue
#pragma unroll
        for (int i = 0; i < 2; i++)
#pragma unroll
            for (int j = 0; j < 4; j++) {
                int r  = row0 + wm*32 + 16*i + group;
                int cc = wn*32 + 8*j + 2*tig;
                if (tile == 0) {
                    float b0 = bg[cc], b1 = bg[cc+1];
                    float2 o0; o0.x = sigmoidf_(acc[i][j][0] + b0); o0.y = sigmoidf_(acc[i][j][1] + b1);
                    float2 o1; o1.x = sigmoidf_(acc[i][j][2] + b0); o1.y = sigmoidf_(acc[i][j][3] + b1);
                    *(float2*)(g_fg + (size_t)r       * DHID + cc) = o0;
                    *(float2*)(g_fg + (size_t)(r + 8) * DHID + cc) = o1;
                } else if (tile == 3) {
                    float b0 = bog[cc], b1 = bog[cc+1];
                    float2 o0; o0.x = sigmoidf_(acc[i][j][0] + b0); o0.y = sigmoidf_(acc[i][j][1] + b1);
                    float2 o1; o1.x = sigmoidf_(acc[i][j][2] + b0); o1.y = sigmoidf_(acc[i][j][3] + b1);
                    *(float2*)(g_og + (size_t)r       * DHID + cc) = o0;
                    *(float2*)(g_og + (size_t)(r + 8) * DHID + cc) = o1;
                } else {
                    int mg = (tile - 1) * 32 + (cc >> 1);
                    float b0 = bg[64 + mg], b1 = bg[128 + mg];
                    float hr0 = sigmoidf_(acc[i][j][0] + b0) * tanhf(acc[i][j][1] + b1);
                    float hr1 = sigmoidf_(acc[i][j][2] + b0) * tanhf(acc[i][j][3] + b1);
                    g_hr[(size_t)r       * DHID + mg] = hr0;
                    g_hr[(size_t)(r + 8) * DHID + mg] = hr1;
                }
            }
    }
}

// ============================================================================
// scan: chunk aggregates, hierarchical combine (round-9 versions)
// ============================================================================
__global__ void scan_pass1()
{
    int b = blockIdx.x;
    int j = threadIdx.x;
    size_t base = (size_t)b * LCH * DHID + j;
    float A = 1.f, B = 0.f;
#pragma unroll 8
    for (int t = 0; t < LCH; t++) {
        size_t idx = base + (size_t)t * DHID;
        float a = g_fg[idx];
        float h = g_hr[idx];
        B = fmaf(B, a, h);
        A *= a;
    }
    g_aggA[b*DHID + j] = A;
    g_aggB[b*DHID + j] = B;
}

__global__ void combine1()
{
    int g = blockIdx.x, j = threadIdx.x;
    float A = 1.f, B = 0.f;
#pragma unroll 8
    for (int c = 0; c < GSZ; c++) {
        int idx = (g*GSZ + c)*DHID + j;
        float a = g_aggA[idx], b = g_aggB[idx];
        B = fmaf(B, a, b);
        A *= a;
    }
    g_gA[g*DHID + j] = A;
    g_gB[g*DHID + j] = B;
}

__global__ void combine2()
{
    int j = threadIdx.x;
    float c = 0.f;
#pragma unroll
    for (int g = 0; g < NGRP; g++) {
        g_gc[g*DHID + j] = c;
        c = fmaf(c, g_gA[g*DHID + j], g_gB[g*DHID + j]);
    }
}

__global__ void combine3()
{
    int g = blockIdx.x, j = threadIdx.x;
    float c = g_gc[g*DHID + j];
#pragma unroll 8
    for (int cc = 0; cc < GSZ; cc++) {
        int idx = (g*GSZ + cc)*DHID + j;
        g_carry[idx] = c;
        c = fmaf(c, g_aggA[idx], g_aggB[idx]);
    }
}

// ============================================================================
// lstm_apply_gemm: 4-way parallel in-chunk scan -> y = og*c (bf16 split in
// smem) -> o = y @ W_c + b_c.
// 256 threads = 4 sub-chunk groups x 64 cols. Sub-chunk aggregates in
// parallel (32-step chains), 4-step serial carry combine, parallel apply.
// ============================================================================
#define LA_SY 72
#define LA_SW 72
#define LA_SMEM ((128*LA_SY*2 + 64*LA_SW*2)*2)

__global__ void __launch_bounds__(256) lstm_apply_gemm(
    const float* __restrict__ Wc, const float* __restrict__ bc)
{
    extern __shared__ __nv_bfloat16 dynsm2[];
    __nv_bfloat16* sYh = dynsm2;
    __nv_bfloat16* sYl = sYh + 128*LA_SY;
    __nv_bfloat16* sWh = sYl + 128*LA_SY;
    __nv_bfloat16* sWl = sWh + 64*LA_SW;
    __shared__ float sA[4][DHID], sB[4][DHID], sC[4][DHID];

    const int b   = blockIdx.x;
    const int tid = threadIdx.x;
    const int lane = tid & 31, warp = tid >> 5;
    const int wm = warp & 3, wn = warp >> 2;
    const int sg = tid >> 6;        // sub-chunk group 0..3
    const int jc = tid & 63;        // column 0..63

    // stage W_c (64x64) hi/lo
#pragma unroll
    for (int it = 0; it < 4; it++) {
        int c = it*256 + tid; int k = c >> 4; int n4 = (c & 15) * 4;
        float4 v = *(const float4*)(Wc + (size_t)k*64 + n4);
        __nv_bfloat162 h01, l01, h23, l23;
        split2(v.x, v.y, h01, l01);
        split2(v.z, v.w, h23, l23);
        *(__nv_bfloat162*)(sWh + k*LA_SW + n4)     = h01;
        *(__nv_bfloat162*)(sWh + k*LA_SW + n4 + 2) = h23;
        *(__nv_bfloat162*)(sWl + k*LA_SW + n4)     = l01;
        *(__nv_bfloat162*)(sWl + k*LA_SW + n4 + 2) = l23;
    }

    // Phase A: sub-chunk aggregates (all 256 threads, 32-step chains)
    {
        size_t base = (size_t)b * LCH * DHID + (size_t)(sg * 32) * DHID + jc;
        float Aa = 1.f, Bb = 0.f;
#pragma unroll 8
        for (int t = 0; t < 32; t++) {
            size_t idx = base + (size_t)t * DHID;
            float a = g_fg[idx];
            float h = g_hr[idx];
            Bb = fmaf(Bb, a, h);
            Aa *= a;
        }
        sA[sg][jc] = Aa;
        sB[sg][jc] = Bb;
    }
    __syncthreads();

    // Phase B: 4-step serial carry combine (64 threads)
    if (tid < DHID) {
        float c = g_carry[b*DHID + tid];
#pragma unroll
        for (int s = 0; s < 4; s++) {
            sC[s][tid] = c;
            c = fmaf(c, sA[s][tid], sB[s][tid]);
        }
    }
    __syncthreads();

    // Phase C: parallel apply + y split into smem
    {
        float c = sC[sg][jc];
        size_t base = (size_t)b * LCH * DHID + (size_t)(sg * 32) * DHID + jc;
#pragma unroll 8
        for (int t = 0; t < 32; t++) {
            size_t idx = base + (size_t)t * DHID;
            c = fmaf(c, g_fg[idx], g_hr[idx]);
            float y = g_og[idx] * c;
            __nv_bfloat16 yh, yl;
            split1(y, yh, yl);
            int tr = sg * 32 + t;
            sYh[tr*LA_SY + jc] = yh;
            sYl[tr*LA_SY + jc] = yl;
        }
    }
    __syncthreads();

    const uint32_t bYh = (uint32_t)__cvta_generic_to_shared(sYh);
    const uint32_t bYl = (uint32_t)__cvta_generic_to_shared(sYl);
    const uint32_t bWh = (uint32_t)__cvta_generic_to_shared(sWh);
    const uint32_t bWl = (uint32_t)__cvta_generic_to_shared(sWl);

    float acc[2][4][4];
#pragma unroll
    for (int i = 0; i < 2; i++)
#pragma unroll
        for (int j = 0; j < 4; j++)
#pragma unroll
            for (int q = 0; q < 4; q++) acc[i][j][q] = 0.f;

    const int lrow = lane & 15;
    const int lcol = (lane >> 4) * 8;

#pragma unroll
    for (int ks = 0; ks < 4; ks++) {
        const int kk = ks * 16;
        uint32_t ah[2][4], al[2][4], bh[4][2], bl[4][2];
#pragma unroll
        for (int i = 0; i < 2; i++) {
            uint32_t off = (uint32_t)(((wm*32 + 16*i + lrow) * LA_SY + kk + lcol) * 2);
            ldsm4(ah[i], bYh + off);
            ldsm4(al[i], bYl + off);
        }
#pragma unroll
        for (int j2 = 0; j2 < 2; j2++) {
            uint32_t off = (uint32_t)(((kk + lrow) * LA_SW + wn*32 + 16*j2 + lcol) * 2);
            uint32_t tr[4];
            ldsm4t(tr, bWh + off);
            bh[2*j2][0] = tr[0]; bh[2*j2][1] = tr[1];
            bh[2*j2+1][0] = tr[2]; bh[2*j2+1][1] = tr[3];
            ldsm4t(tr, bWl + off);
            bl[2*j2][0] = tr[0]; bl[2*j2][1] = tr[1];
            bl[2*j2+1][0] = tr[2]; bl[2*j2+1][1] = tr[3];
        }
#pragma unroll
        for (int i = 0; i < 2; i++)
#pragma unroll
            for (int j = 0; j < 4; j++) {
                mma16816(acc[i][j], ah[i], bh[j]);
                mma16816(acc[i][j], ah[i], bl[j]);
                mma16816(acc[i][j], al[i], bh[j]);
            }
    }

    const int group = lane >> 2, tig = lane & 3;
#pragma unroll
    for (int i = 0; i < 2; i++)
#pragma unroll
        for (int j = 0; j < 4; j++) {
            int r  = b*128 + wm*32 + 16*i + group;
            int cc = wn*32 + 8*j + 2*tig;
            float b0 = bc[cc], b1 = bc[cc+1];
            float2 o0; o0.x = acc[i][j][0] + b0; o0.y = acc[i][j][1] + b1;
            float2 o1; o1.x = acc[i][j][2] + b0; o1.y = acc[i][j][3] + b1;
            *(float2*)(g_o + (size_t)r       * DOUT + cc) = o0;
            *(float2*)(g_o + (size_t)(r + 8) * DOUT + cc) = o1;
        }
}

// ---------------- launch ----------------
extern "C" void kernel_launch(void* const* d_in, const int* in_sizes, int n_in,
                              void* d_out, int out_size)
{
    const float* inputs  = (const float*)d_in[0];
    const float* W_in    = (const float*)d_in[1];
    const float* b_in    = (const float*)d_in[2];
    const float* W_gates = (const float*)d_in[3];
    const float* b_gates = (const float*)d_in[4];
    const float* W_og    = (const float*)d_in[5];
    const float* b_og    = (const float*)d_in[6];
    const float* W_c     = (const float*)d_in[7];
    const float* b_c     = (const float*)d_in[8];
    const float* W_out   = (const float*)d_in[9];
    const float* b_out   = (const float*)d_in[10];
    float* out = (float*)d_out;

    float *px, *po;
    cudaGetSymbolAddress((void**)&px, g_x);
    cudaGetSymbolAddress((void**)&po, g_o);

    cudaFuncSetAttribute(gemm_big, cudaFuncAttributeMaxDynamicSharedMemorySize, GB_SMEM);
    cudaFuncSetAttribute(gemm_gates, cudaFuncAttributeMaxDynamicSharedMemorySize, GG_SMEM);
    cudaFuncSetAttribute(lstm_apply_gemm, cudaFuncAttributeMaxDynamicSharedMemorySize, LA_SMEM);

    dim3 blk(256);

    // 1) x = inputs @ W_in + b_in           (32768 x 512 x 512)
    gemm_big<<<dim3(DMODEL/GB_BN, SEQ/GB_BM), blk, GB_SMEM>>>(
        inputs, W_in, b_in, px, SEQ, DMODEL, DMODEL);

    // 2) fused gates: fg, hr, og           (262144 rows, K=64), A staged once
    gemm_gates<<<NROWS/128, blk, GG_SMEM>>>(px, W_gates, b_gates, W_og, b_og);

    // 3) chunk aggregates + hierarchical combine
    scan_pass1<<<NCH, DHID>>>();
    combine1<<<NGRP, DHID>>>();
    combine2<<<1, DHID>>>();
    combine3<<<NGRP, DHID>>>();

    // 4) fused scan-apply (4-way parallel) + o = y @ W_c + b_c
    lstm_apply_gemm<<<NCH, blk, LA_SMEM>>>(W_c, b_c);

    // 5) out = o @ W_out + b_out            (32768 x 512 x 512)
    gemm_big<<<dim3(DMODEL/GB_BN, SEQ/GB_BM), blk, GB_SMEM>>>(
        po, W_out, b_out, out, SEQ, DMODEL, DMODEL);
}